// round 5
// baseline (speedup 1.0000x reference)
#include <cuda_runtime.h>
#include <math.h>

#define BB 32
#define PP 64
#define LL 64
#define VV 32000

// Scratch (no allocations allowed). Zero-initialized at module load.
// g_flag is reset to 0 by k_final each run; everything else is plain-stored
// unconditionally every run (no init needed).
__device__ uint2 g_mask[BB * PP];    // truth bitmask per (b,i)
__device__ int   g_flag[BB];         // DP-done flag per batch
__device__ float g_sum[BB * PP];     // per-row sum over V
__device__ float g_S[BB * PP];       // per-row sum of outputs at distinct argmins
__device__ int   g_m[BB * PP];       // per-row distinct argmin count

// ---------------------------------------------------------------------------
// k_main: one block per (b,i) row. NO doubles anywhere (keeps regs <= 32).
//   blocks 0..31: warp 0 first runs the edit-distance DP for batch blockIdx.x
//                 (registers + shuffles only), publishes g_mask + g_flag.
//   all blocks : stream-sum their 128KB outputs row (fp32), wait on flag[b],
//                dedup-gather distinct argmin symbols (L2-hot), plain-store
//                (sum, S, m) for this row.
// ---------------------------------------------------------------------------
__global__ void __launch_bounds__(256, 8)
k_main(const float* __restrict__ outputs,
       const int* __restrict__ syms,
       const int* __restrict__ targets,
       const unsigned char* __restrict__ mask) {
    const unsigned FULL = 0xffffffffu;
    int bp   = blockIdx.x;           // 0..2047
    int b    = bp >> 6;
    int tid  = threadIdx.x;
    int lane = tid & 31, wid = tid >> 5;

    // ---------------- DP (blocks 0..31, warp 0 only) ----------------
    if (bp < BB && wid == 0) {
        int bd = bp;
        int j0 = 2 * lane, j1 = 2 * lane + 1;
        int tg0 = targets[bd * LL + j0];
        int tg1 = targets[bd * LL + j1];
        int mk0 = mask[bd * LL + j0];
        int mk1 = mask[bd * LL + j1];
        int s0  = syms[bd * PP + j0];
        int s1  = syms[bd * PP + j1];
        int tgm1 = __shfl_up_sync(FULL, tg1, 1);   // tg[j0-1]
        float p0 = (float)j0, p1 = (float)j1;      // row 0 (exact ints in fp32)

        for (int i = 0; i < PP; i++) {
            float d0, d1;
            if (i == 0) {
                d0 = p0; d1 = p1;
            } else {
                int im1 = i - 1;
                int sym = __shfl_sync(FULL, (im1 & 1) ? s1 : s0, im1 >> 1);
                float p1m = __shfl_up_sync(FULL, p1, 1);    // prev[j0-1]
                float tmp0 = (lane == 0) ? (float)i
                           : fminf(p1m + ((sym != tgm1) ? 1.0f : 0.0f), p0 + 1.0f);
                float tmp1 = fminf(p0 + ((sym != tg0) ? 1.0f : 0.0f), p1 + 1.0f);
                float v0 = tmp0 - (float)j0;
                float sB = fminf(v0, tmp1 - (float)j1);     // pair-inclusive
                float sc = sB;
                #pragma unroll
                for (int off = 1; off < 32; off <<= 1) {
                    float o = __shfl_up_sync(FULL, sc, off);
                    if (lane >= off) sc = fminf(sc, o);
                }
                float e = __shfl_up_sync(FULL, sc, 1);      // exclusive prefix
                if (lane == 0) e = INFINITY;
                d0 = (float)j0 + fminf(e, v0);
                d1 = (float)j1 + fminf(e, sB);
                p0 = d0; p1 = d1;
            }
            float md0 = mk0 ? d0 : INFINITY;
            float md1 = mk1 ? d1 : INFINITY;
            float mv = fminf(md0, md1);
            #pragma unroll
            for (int off = 16; off; off >>= 1)
                mv = fminf(mv, __shfl_xor_sync(FULL, mv, off));
            unsigned mE = __ballot_sync(FULL, md0 == mv);
            unsigned mO = __ballot_sync(FULL, md1 == mv);
            if (lane == 0) g_mask[bd * PP + i] = make_uint2(mE, mO);
        }
        __threadfence();
        if (lane == 0) atomicExch(&g_flag[bd], 1);
    }

    // ---------------- rowsum (all blocks, HBM-bound, fp32) ----------
    const float4* row4 = (const float4*)(outputs + (size_t)bp * VV);
    float acc = 0.0f;
    {
        int idx = tid;
        #pragma unroll 4
        for (int k = 0; k < 31; k++, idx += 256) {      // 31*256 = 7936 float4
            float4 v = row4[idx];
            acc += (v.x + v.y) + (v.z + v.w);
        }
        if (tid < (VV / 4 - 7936)) {                    // tail: 64 float4
            float4 v = row4[7936 + tid];
            acc += (v.x + v.y) + (v.z + v.w);
        }
    }
    #pragma unroll
    for (int off = 16; off; off >>= 1)
        acc += __shfl_down_sync(FULL, acc, off);
    __shared__ float sred[8];
    if (lane == 0) sred[wid] = acc;

    // ---------------- wait for this batch's DP mask ----------------
    if (tid == 0) {
        while (atomicAdd(&g_flag[b], 0) == 0) __nanosleep(64);
    }
    __syncthreads();
    __threadfence();

    // ---------------- dedup gather of distinct argmin symbols ------
    __shared__ int stg[LL];
    __shared__ unsigned char str[LL];
    if (tid < LL) {
        stg[tid] = targets[b * LL + tid];
        uint2 m = g_mask[bp];
        str[tid] = (unsigned char)((((tid & 1) ? m.y : m.x) >> (tid >> 1)) & 1);
    }
    __syncthreads();

    float contrib = 0.0f, cm = 0.0f;
    if (tid < LL && str[tid]) {
        int tv = stg[tid];
        bool first = true;
        for (int k = 0; k < tid; k++)
            if (str[k] && stg[k] == tv) { first = false; break; }
        if (first) {
            contrib = outputs[(size_t)bp * VV + tv];   // L2-hot: row just streamed
            cm = 1.0f;
        }
    }
    #pragma unroll
    for (int off = 16; off; off >>= 1) {
        contrib += __shfl_down_sync(FULL, contrib, off);
        cm      += __shfl_down_sync(FULL, cm, off);
    }
    __shared__ float sc2[2], sm2[2];
    if (tid < LL && lane == 0) { sc2[wid] = contrib; sm2[wid] = cm; }
    __syncthreads();

    if (tid == 0) {
        float s = 0.0f;
        #pragma unroll
        for (int w = 0; w < 8; w++) s += sred[w];
        g_sum[bp] = s;
        g_S[bp]   = sc2[0] + sc2[1];
        g_m[bp]   = (int)(sm2[0] + sm2[1]);
    }
}

// ---------------------------------------------------------------------------
// k_final: all double math lives here. Deterministic (no atomics).
// warp w handles batch w; lane l handles rows l and l+32.
// Analytic collapse: p1=e/D, p0=1/D, D=(V-m)+m*e; ln p1=1-lnD, ln p0=-lnD.
// kl = m*p1*(1-lnD) - (V-m)*p0*lnD - p0*sumAll - (p1-p0)*Ssum
// Also resets g_flag for the next graph replay.
// ---------------------------------------------------------------------------
__global__ void k_final(float* __restrict__ out,
                        const unsigned char* __restrict__ mask) {
    const double E1 = 2.718281828459045235360287;
    int w = threadIdx.x >> 5;        // batch (32 warps)
    int l = threadIdx.x & 31;

    double acc = 0.0;
    float  cnt = 0.0f;
    #pragma unroll
    for (int h = 0; h < 2; h++) {
        int i  = l + 32 * h;
        int bp = w * PP + i;
        if (mask[w * LL + i]) {
            double m   = (double)g_m[bp];
            double D   = ((double)VV - m) + m * E1;
            double lnD = log(D);
            double p1  = E1 / D;
            double pz  = 1.0 / D;
            acc += m * p1 * (1.0 - lnD) - ((double)VV - m) * pz * lnD
                 - pz * (double)g_sum[bp] - (p1 - pz) * (double)g_S[bp];
            cnt += 1.0f;
        }
    }
    #pragma unroll
    for (int off = 16; off; off >>= 1) {
        acc += __shfl_down_sync(0xffffffffu, acc, off);
        cnt += __shfl_down_sync(0xffffffffu, cnt, off);
    }

    __shared__ double spb[BB];
    __shared__ float  sne[BB];
    if (l == 0) {
        spb[w] = acc / ((double)cnt + 1e-13);
        sne[w] = (cnt > 0.0f) ? 1.0f : 0.0f;
        g_flag[w] = 0;               // reset handshake for next replay
    }
    __syncthreads();

    if (threadIdx.x < 32) {
        double pb = spb[threadIdx.x];
        float  ne = sne[threadIdx.x];
        #pragma unroll
        for (int off = 16; off; off >>= 1) {
            pb += __shfl_down_sync(0xffffffffu, pb, off);
            ne += __shfl_down_sync(0xffffffffu, ne, off);
        }
        if (threadIdx.x == 0) out[0] = (float)(pb / ((double)ne + 1e-13));
    }
}

// ---------------------------------------------------------------------------
extern "C" void kernel_launch(void* const* d_in, const int* in_sizes, int n_in,
                              void* d_out, int out_size) {
    const float*         outputs = (const float*)d_in[0];
    const int*           syms    = (const int*)d_in[1];
    const int*           targets = (const int*)d_in[2];
    const unsigned char* mask    = (const unsigned char*)d_in[3];

    k_main<<<BB * PP, 256>>>(outputs, syms, targets, mask);
    k_final<<<1, 1024>>>((float*)d_out, mask);
}

// round 6
// speedup vs baseline: 1.1669x; 1.1669x over previous
#include <cuda_runtime.h>
#include <math.h>

#define BB 32
#define PP 64
#define LL 64
#define VV 32000

// Scratch (no allocations allowed). Zero-initialized at module load.
// g_flag / g_done are reset by the last block each run (graph-replay safe).
__device__ uint2    g_mask[BB * PP];   // truth bitmask per (b,i)
__device__ int      g_flag[BB];        // DP-done flag per batch
__device__ float    g_sum[BB * PP];    // per-row sum over V
__device__ float    g_S[BB * PP];      // per-row sum at distinct argmins
__device__ int      g_m[BB * PP];      // per-row distinct argmin count
__device__ unsigned g_done;            // block completion counter

// ---------------------------------------------------------------------------
// Single kernel, grid = 1024 blocks x 256 thr (one wave, fully resident).
// Block q handles rows 2q and 2q+1 (same batch b = q>>5).
//   blocks 0..31 : warp 0 first runs the edit-distance DP for batch blockIdx.x
//                  (registers + shuffles only), publishes g_mask + g_flag.
//   all blocks   : per row: stream-sum 128KB (fp32, HBM-bound), dedup-gather
//                  distinct argmin symbols (L2-hot), plain-store (sum,S,m).
//   last block   : fp32 analytic KL per row (log1p polynomial — NO fp64, NO
//                  log()), deterministic reduction, writes scalar, resets flags.
//
// Analytic collapse: q has 2 levels -> p1=e/D, p0=1/D, D=(V-m)+m*e.
// lnD = ln(V) + log1p(m*(e-1)/V);  ln p1 = 1-lnD;  ln p0 = -lnD.
// kl = m*p1*(1-lnD) - (V-m)*p0*lnD - p0*sumAll - (p1-p0)*Ssum
// ---------------------------------------------------------------------------
__global__ void __launch_bounds__(256, 8)
k_main(const float* __restrict__ outputs,
       const int* __restrict__ syms,
       const int* __restrict__ targets,
       const unsigned char* __restrict__ mask,
       float* __restrict__ out) {
    const unsigned FULL = 0xffffffffu;
    int q    = blockIdx.x;            // 0..1023
    int b    = q >> 5;                // batch of both rows
    int tid  = threadIdx.x;
    int lane = tid & 31, wid = tid >> 5;

    // ---------------- DP (blocks 0..31, warp 0 only) ----------------
    if (q < BB && wid == 0) {
        int bd = q;
        int j0 = 2 * lane, j1 = 2 * lane + 1;
        int tg0 = targets[bd * LL + j0];
        int tg1 = targets[bd * LL + j1];
        int mk0 = mask[bd * LL + j0];
        int mk1 = mask[bd * LL + j1];
        int s0  = syms[bd * PP + j0];
        int s1  = syms[bd * PP + j1];
        int tgm1 = __shfl_up_sync(FULL, tg1, 1);   // tg[j0-1]
        float p0 = (float)j0, p1 = (float)j1;      // row 0 (exact ints in fp32)

        for (int i = 0; i < PP; i++) {
            float d0, d1;
            if (i == 0) {
                d0 = p0; d1 = p1;
            } else {
                int im1 = i - 1;
                int sym = __shfl_sync(FULL, (im1 & 1) ? s1 : s0, im1 >> 1);
                float p1m = __shfl_up_sync(FULL, p1, 1);    // prev[j0-1]
                float tmp0 = (lane == 0) ? (float)i
                           : fminf(p1m + ((sym != tgm1) ? 1.0f : 0.0f), p0 + 1.0f);
                float tmp1 = fminf(p0 + ((sym != tg0) ? 1.0f : 0.0f), p1 + 1.0f);
                float v0 = tmp0 - (float)j0;
                float sB = fminf(v0, tmp1 - (float)j1);     // pair-inclusive
                float sc = sB;
                #pragma unroll
                for (int off = 1; off < 32; off <<= 1) {
                    float o = __shfl_up_sync(FULL, sc, off);
                    if (lane >= off) sc = fminf(sc, o);
                }
                float e = __shfl_up_sync(FULL, sc, 1);      // exclusive prefix
                if (lane == 0) e = INFINITY;
                d0 = (float)j0 + fminf(e, v0);
                d1 = (float)j1 + fminf(e, sB);
                p0 = d0; p1 = d1;
            }
            float md0 = mk0 ? d0 : INFINITY;
            float md1 = mk1 ? d1 : INFINITY;
            float mv = fminf(md0, md1);
            #pragma unroll
            for (int off = 16; off; off >>= 1)
                mv = fminf(mv, __shfl_xor_sync(FULL, mv, off));
            unsigned mE = __ballot_sync(FULL, md0 == mv);
            unsigned mO = __ballot_sync(FULL, md1 == mv);
            if (lane == 0) g_mask[bd * PP + i] = make_uint2(mE, mO);
        }
        __threadfence();
        if (lane == 0) atomicExch(&g_flag[bd], 1);
    }

    // ---------------- wait once for this batch's DP mask ------------
    if (tid == 0) {
        while (atomicAdd(&g_flag[b], 0) == 0) __nanosleep(64);
    }
    __syncthreads();
    __threadfence();

    __shared__ float sred[8];
    __shared__ int   stg[LL];
    __shared__ unsigned char str[LL];
    __shared__ float sc2[2], sm2[2];

    if (tid < LL) stg[tid] = targets[b * LL + tid];

    #pragma unroll
    for (int r = 0; r < 2; r++) {
        int bp = 2 * q + r;

        // -------- rowsum (HBM-bound, fp32) --------
        const float4* row4 = (const float4*)(outputs + (size_t)bp * VV);
        float acc = 0.0f;
        {
            int idx = tid;
            #pragma unroll 4
            for (int k = 0; k < 31; k++, idx += 256) {     // 31*256 = 7936
                float4 v = row4[idx];
                acc += (v.x + v.y) + (v.z + v.w);
            }
            if (tid < (VV / 4 - 7936)) {                   // tail: 64 float4
                float4 v = row4[7936 + tid];
                acc += (v.x + v.y) + (v.z + v.w);
            }
        }
        #pragma unroll
        for (int off = 16; off; off >>= 1)
            acc += __shfl_down_sync(FULL, acc, off);
        if (lane == 0) sred[wid] = acc;

        // -------- dedup gather of distinct argmin symbols --------
        if (tid < LL) {
            uint2 m = g_mask[bp];
            str[tid] = (unsigned char)((((tid & 1) ? m.y : m.x) >> (tid >> 1)) & 1);
        }
        __syncthreads();

        float contrib = 0.0f, cm = 0.0f;
        if (tid < LL && str[tid]) {
            int tv = stg[tid];
            bool first = true;
            for (int k = 0; k < tid; k++)
                if (str[k] && stg[k] == tv) { first = false; break; }
            if (first) {
                contrib = outputs[(size_t)bp * VV + tv];   // L2-hot
                cm = 1.0f;
            }
        }
        #pragma unroll
        for (int off = 16; off; off >>= 1) {
            contrib += __shfl_down_sync(FULL, contrib, off);
            cm      += __shfl_down_sync(FULL, cm, off);
        }
        if (tid < LL && lane == 0) { sc2[wid] = contrib; sm2[wid] = cm; }
        __syncthreads();

        if (tid == 0) {
            float s = 0.0f;
            #pragma unroll
            for (int w = 0; w < 8; w++) s += sred[w];
            g_sum[bp] = s;
            g_S[bp]   = sc2[0] + sc2[1];
            g_m[bp]   = (int)(sm2[0] + sm2[1]);
        }
        __syncthreads();   // protect shared reuse across rows
    }

    // ---------------- last-block finisher (all fp32) ----------------
    __shared__ int s_last;
    if (tid == 0) {
        __threadfence();
        unsigned prev = atomicAdd(&g_done, 1u);
        s_last = (prev == (unsigned)(gridDim.x - 1));
    }
    __syncthreads();
    if (!s_last) return;

    // thread t = bb*8 + s : batch bb, rows i = s + 8*k (k<8). Deterministic.
    const float E1f  = 2.71828182845904523f;
    const float EM1V = 1.71828182845904523f / 32000.0f;
    const float LNV  = 10.37349118f;                 // ln(32000)
    int bb = tid >> 3, sl = tid & 7;

    float kacc = 0.0f, cnt = 0.0f;
    #pragma unroll
    for (int k = 0; k < 8; k++) {
        int i  = sl + 8 * k;
        int bp = bb * PP + i;
        if (mask[bb * LL + i]) {
            float mm  = (float)g_m[bp];
            float D   = ((float)VV - mm) + mm * E1f;
            float p0  = 1.0f / D;
            float p1  = E1f * p0;
            float x   = mm * EM1V;
            float l1p = x * (1.0f + x * (-0.5f + x * (0.33333333f + x * -0.25f)));
            float lnD = LNV + l1p;
            kacc += mm * p1 * (1.0f - lnD) - ((float)VV - mm) * p0 * lnD
                  - p0 * g_sum[bp] - (p1 - p0) * g_S[bp];
            cnt  += 1.0f;
        }
    }
    __shared__ float spart[256], scnt[256];
    spart[tid] = kacc; scnt[tid] = cnt;
    __syncthreads();

    if (tid < BB) {
        float s = 0.0f, w = 0.0f;
        #pragma unroll
        for (int k = 0; k < 8; k++) { s += spart[tid * 8 + k]; w += scnt[tid * 8 + k]; }
        float pb = s / (w + 1e-13f);
        float ne = (w > 0.0f) ? 1.0f : 0.0f;
        #pragma unroll
        for (int off = 16; off; off >>= 1) {
            pb += __shfl_down_sync(FULL, pb, off);
            ne += __shfl_down_sync(FULL, ne, off);
        }
        if (tid == 0) out[0] = pb / (ne + 1e-13f);
        g_flag[tid] = 0;                   // reset handshake for next replay
        if (tid == 0) g_done = 0u;
    }
}

// ---------------------------------------------------------------------------
extern "C" void kernel_launch(void* const* d_in, const int* in_sizes, int n_in,
                              void* d_out, int out_size) {
    const float*         outputs = (const float*)d_in[0];
    const int*           syms    = (const int*)d_in[1];
    const int*           targets = (const int*)d_in[2];
    const unsigned char* mask    = (const unsigned char*)d_in[3];

    k_main<<<BB * PP / 2, 256>>>(outputs, syms, targets, mask, (float*)d_out);
}

// round 7
// speedup vs baseline: 1.4443x; 1.2378x over previous
#include <cuda_runtime.h>
#include <math.h>

#define BB 32
#define PP 64
#define LL 64
#define VV 32000

// Scratch (no allocations allowed). Zero-initialized at module load.
// g_flag / g_done are reset by the last block each run (graph-replay safe).
__device__ uint2    g_mask[BB * PP];   // truth bitmask per (b,i)
__device__ int      g_flag[BB];        // DP-done flag per batch
__device__ float    g_sum[BB * PP];    // per-row sum over V
__device__ float    g_S[BB * PP];      // per-row sum at distinct argmins
__device__ int      g_m[BB * PP];      // per-row distinct argmin count
__device__ unsigned g_done;            // block completion counter

// ---------------------------------------------------------------------------
// Single kernel, grid = 1024 x 256 (ONE wave, fully resident at 8 blk/SM).
// Block q owns rows 2q, 2q+1 (same batch b = q>>5).
// Order inside a block: STREAM BOTH ROWS FIRST (interleaved, max MLP),
// then wait on the DP flag (already set by then), then epilogue.
//   blocks 0..31 : warp 0 additionally runs the edit-distance DP for batch q
//                  before joining the stream (registers + shuffles only).
//   last block   : fp32 analytic-KL finisher (log1p polynomial, no fp64),
//                  deterministic reduction, writes scalar, resets flags.
//
// Analytic collapse: q has 2 levels -> p1=e/D, p0=1/D, D=(V-m)+m*e.
// lnD = ln(V) + log1p(m*(e-1)/V);  ln p1 = 1-lnD;  ln p0 = -lnD.
// kl = m*p1*(1-lnD) - (V-m)*p0*lnD - p0*sumAll - (p1-p0)*Ssum
// ---------------------------------------------------------------------------
__global__ void __launch_bounds__(256, 8)
k_main(const float* __restrict__ outputs,
       const int* __restrict__ syms,
       const int* __restrict__ targets,
       const unsigned char* __restrict__ mask,
       float* __restrict__ out) {
    const unsigned FULL = 0xffffffffu;
    int q    = blockIdx.x;            // 0..1023
    int b    = q >> 5;                // batch of both rows
    int tid  = threadIdx.x;
    int lane = tid & 31, wid = tid >> 5;

    // ---------------- DP (blocks 0..31, warp 0 only) ----------------
    if (q < BB && wid == 0) {
        int bd = q;
        int j0 = 2 * lane, j1 = 2 * lane + 1;
        int tg0 = targets[bd * LL + j0];
        int tg1 = targets[bd * LL + j1];
        int mk0 = mask[bd * LL + j0];
        int mk1 = mask[bd * LL + j1];
        int s0  = syms[bd * PP + j0];
        int s1  = syms[bd * PP + j1];
        int tgm1 = __shfl_up_sync(FULL, tg1, 1);   // tg[j0-1]
        float p0 = (float)j0, p1 = (float)j1;      // row 0 (exact ints in fp32)

        for (int i = 0; i < PP; i++) {
            float d0, d1;
            if (i == 0) {
                d0 = p0; d1 = p1;
            } else {
                int im1 = i - 1;
                int sym = __shfl_sync(FULL, (im1 & 1) ? s1 : s0, im1 >> 1);
                float p1m = __shfl_up_sync(FULL, p1, 1);    // prev[j0-1]
                float tmp0 = (lane == 0) ? (float)i
                           : fminf(p1m + ((sym != tgm1) ? 1.0f : 0.0f), p0 + 1.0f);
                float tmp1 = fminf(p0 + ((sym != tg0) ? 1.0f : 0.0f), p1 + 1.0f);
                float v0 = tmp0 - (float)j0;
                float sB = fminf(v0, tmp1 - (float)j1);     // pair-inclusive
                float sc = sB;
                #pragma unroll
                for (int off = 1; off < 32; off <<= 1) {
                    float o = __shfl_up_sync(FULL, sc, off);
                    if (lane >= off) sc = fminf(sc, o);
                }
                float e = __shfl_up_sync(FULL, sc, 1);      // exclusive prefix
                if (lane == 0) e = INFINITY;
                d0 = (float)j0 + fminf(e, v0);
                d1 = (float)j1 + fminf(e, sB);
                p0 = d0; p1 = d1;
            }
            float md0 = mk0 ? d0 : INFINITY;
            float md1 = mk1 ? d1 : INFINITY;
            float mv = fminf(md0, md1);
            #pragma unroll
            for (int off = 16; off; off >>= 1)
                mv = fminf(mv, __shfl_xor_sync(FULL, mv, off));
            unsigned mE = __ballot_sync(FULL, md0 == mv);
            unsigned mO = __ballot_sync(FULL, md1 == mv);
            if (lane == 0) g_mask[bd * PP + i] = make_uint2(mE, mO);
        }
        __threadfence();
        if (lane == 0) atomicExch(&g_flag[bd], 1);
    }

    // -------- stream BOTH rows, interleaved (HBM-bound, fp32) --------
    int bp0 = 2 * q, bp1 = 2 * q + 1;
    const float4* r0 = (const float4*)(outputs + (size_t)bp0 * VV);
    const float4* r1 = (const float4*)(outputs + (size_t)bp1 * VV);
    float acc0 = 0.0f, acc1 = 0.0f;
    {
        int idx = tid;
        #pragma unroll 2
        for (int k = 0; k < 31; k++, idx += 256) {          // 31*256 = 7936
            float4 a = r0[idx];
            float4 c = r1[idx];
            acc0 += (a.x + a.y) + (a.z + a.w);
            acc1 += (c.x + c.y) + (c.z + c.w);
        }
        if (tid < (VV / 4 - 7936)) {                        // tail: 64 float4
            float4 a = r0[7936 + tid];
            float4 c = r1[7936 + tid];
            acc0 += (a.x + a.y) + (a.z + a.w);
            acc1 += (c.x + c.y) + (c.z + c.w);
        }
    }
    #pragma unroll
    for (int off = 16; off; off >>= 1) {
        acc0 += __shfl_down_sync(FULL, acc0, off);
        acc1 += __shfl_down_sync(FULL, acc1, off);
    }
    __shared__ float sred0[8], sred1[8];
    if (lane == 0) { sred0[wid] = acc0; sred1[wid] = acc1; }

    // -------- wait for this batch's DP mask (already set by now) -----
    if (tid == 0) {
        while (atomicAdd(&g_flag[b], 0) == 0) __nanosleep(64);
    }
    __syncthreads();
    __threadfence();

    // -------- epilogue: dedup gathers for both rows ------------------
    __shared__ int stg[LL];
    __shared__ unsigned char str0[LL], str1[LL];
    if (tid < LL) {
        stg[tid] = targets[b * LL + tid];
        uint2 m0 = g_mask[bp0];
        uint2 m1 = g_mask[bp1];
        str0[tid] = (unsigned char)((((tid & 1) ? m0.y : m0.x) >> (tid >> 1)) & 1);
        str1[tid] = (unsigned char)((((tid & 1) ? m1.y : m1.x) >> (tid >> 1)) & 1);
    }
    __syncthreads();

    float c0 = 0.0f, n0 = 0.0f, c1 = 0.0f, n1 = 0.0f;
    if (tid < LL) {
        int tv = stg[tid];
        if (str0[tid]) {
            bool first = true;
            for (int k = 0; k < tid; k++)
                if (str0[k] && stg[k] == tv) { first = false; break; }
            if (first) { c0 = outputs[(size_t)bp0 * VV + tv]; n0 = 1.0f; }  // L2-hot
        }
        if (str1[tid]) {
            bool first = true;
            for (int k = 0; k < tid; k++)
                if (str1[k] && stg[k] == tv) { first = false; break; }
            if (first) { c1 = outputs[(size_t)bp1 * VV + tv]; n1 = 1.0f; }  // L2-hot
        }
    }
    #pragma unroll
    for (int off = 16; off; off >>= 1) {
        c0 += __shfl_down_sync(FULL, c0, off);
        n0 += __shfl_down_sync(FULL, n0, off);
        c1 += __shfl_down_sync(FULL, c1, off);
        n1 += __shfl_down_sync(FULL, n1, off);
    }
    __shared__ float sS0[2], sm0[2], sS1[2], sm1[2];
    if (tid < LL && lane == 0) { sS0[wid] = c0; sm0[wid] = n0; sS1[wid] = c1; sm1[wid] = n1; }
    __syncthreads();

    if (tid == 0) {
        float s0v = 0.0f, s1v = 0.0f;
        #pragma unroll
        for (int w = 0; w < 8; w++) { s0v += sred0[w]; s1v += sred1[w]; }
        g_sum[bp0] = s0v;            g_sum[bp1] = s1v;
        g_S[bp0]   = sS0[0] + sS0[1]; g_S[bp1]  = sS1[0] + sS1[1];
        g_m[bp0]   = (int)(sm0[0] + sm0[1]);
        g_m[bp1]   = (int)(sm1[0] + sm1[1]);
    }

    // ---------------- last-block finisher (all fp32) ----------------
    __shared__ int s_last;
    if (tid == 0) {
        __threadfence();
        unsigned prev = atomicAdd(&g_done, 1u);
        s_last = (prev == (unsigned)(gridDim.x - 1));
    }
    __syncthreads();
    if (!s_last) return;

    // thread t = bb*8 + s : batch bb, rows i = s + 8*k (k<8). Deterministic.
    const float E1f  = 2.71828182845904523f;
    const float EM1V = 1.71828182845904523f / 32000.0f;
    const float LNV  = 10.37349118f;                 // ln(32000)
    int bb = tid >> 3, sl = tid & 7;

    float kacc = 0.0f, cnt = 0.0f;
    #pragma unroll
    for (int k = 0; k < 8; k++) {
        int i  = sl + 8 * k;
        int bp = bb * PP + i;
        if (mask[bb * LL + i]) {
            float mm  = (float)g_m[bp];
            float D   = ((float)VV - mm) + mm * E1f;
            float p0  = 1.0f / D;
            float p1  = E1f * p0;
            float x   = mm * EM1V;
            float l1p = x * (1.0f + x * (-0.5f + x * (0.33333333f + x * -0.25f)));
            float lnD = LNV + l1p;
            kacc += mm * p1 * (1.0f - lnD) - ((float)VV - mm) * p0 * lnD
                  - p0 * g_sum[bp] - (p1 - p0) * g_S[bp];
            cnt  += 1.0f;
        }
    }
    __shared__ float spart[256], scnt[256];
    spart[tid] = kacc; scnt[tid] = cnt;
    __syncthreads();

    if (tid < BB) {
        float s = 0.0f, w = 0.0f;
        #pragma unroll
        for (int k = 0; k < 8; k++) { s += spart[tid * 8 + k]; w += scnt[tid * 8 + k]; }
        float pb = s / (w + 1e-13f);
        float ne = (w > 0.0f) ? 1.0f : 0.0f;
        #pragma unroll
        for (int off = 16; off; off >>= 1) {
            pb += __shfl_down_sync(FULL, pb, off);
            ne += __shfl_down_sync(FULL, ne, off);
        }
        if (tid == 0) out[0] = pb / (ne + 1e-13f);
        g_flag[tid] = 0;                   // reset handshake for next replay
        if (tid == 0) g_done = 0u;
    }
}

// ---------------------------------------------------------------------------
extern "C" void kernel_launch(void* const* d_in, const int* in_sizes, int n_in,
                              void* d_out, int out_size) {
    const float*         outputs = (const float*)d_in[0];
    const int*           syms    = (const int*)d_in[1];
    const int*           targets = (const int*)d_in[2];
    const unsigned char* mask    = (const unsigned char*)d_in[3];

    k_main<<<BB * PP / 2, 256>>>(outputs, syms, targets, mask, (float*)d_out);
}